// round 2
// baseline (speedup 1.0000x reference)
#include <cuda_runtime.h>
#include <stdint.h>

#define N_ANTS   16384
#define N_NODES  512
#define N_BATCH  4096
#define N_STEPS  511   // N_NODES - 1

// Scratch (no allocation allowed -> __device__ globals)
__device__ uint2  g_subkeys[N_STEPS];
__device__ int    g_paths[N_ANTS * N_NODES];
__device__ float  g_plen[N_ANTS];
__device__ int    g_best;

__device__ __forceinline__ uint32_t rotl(uint32_t x, int d) {
    return __funnelshift_l(x, x, d);   // single SHF
}

// JAX threefry2x32: 20 rounds, 5 key injections. Returns both output words.
__device__ __forceinline__ void threefry2x32(uint32_t ks0, uint32_t ks1, uint32_t ks2,
                                             uint32_t x0, uint32_t x1,
                                             uint32_t& o0, uint32_t& o1)
{
    x0 += ks0; x1 += ks1;
    x0 += x1; x1 = rotl(x1,13); x1 ^= x0;
    x0 += x1; x1 = rotl(x1,15); x1 ^= x0;
    x0 += x1; x1 = rotl(x1,26); x1 ^= x0;
    x0 += x1; x1 = rotl(x1, 6); x1 ^= x0;
    x0 += ks1; x1 += ks2 + 1u;
    x0 += x1; x1 = rotl(x1,17); x1 ^= x0;
    x0 += x1; x1 = rotl(x1,29); x1 ^= x0;
    x0 += x1; x1 = rotl(x1,16); x1 ^= x0;
    x0 += x1; x1 = rotl(x1,24); x1 ^= x0;
    x0 += ks2; x1 += ks0 + 2u;
    x0 += x1; x1 = rotl(x1,13); x1 ^= x0;
    x0 += x1; x1 = rotl(x1,15); x1 ^= x0;
    x0 += x1; x1 = rotl(x1,26); x1 ^= x0;
    x0 += x1; x1 = rotl(x1, 6); x1 ^= x0;
    x0 += ks0; x1 += ks1 + 3u;
    x0 += x1; x1 = rotl(x1,17); x1 ^= x0;
    x0 += x1; x1 = rotl(x1,29); x1 ^= x0;
    x0 += x1; x1 = rotl(x1,16); x1 ^= x0;
    x0 += x1; x1 = rotl(x1,24); x1 ^= x0;
    x0 += ks1; x1 += ks2 + 4u;
    x0 += x1; x1 = rotl(x1,13); x1 ^= x0;
    x0 += x1; x1 = rotl(x1,15); x1 ^= x0;
    x0 += x1; x1 = rotl(x1,26); x1 ^= x0;
    x0 += x1; x1 = rotl(x1, 6); x1 ^= x0;
    x0 += ks2; x1 += ks0 + 5u;
    o0 = x0; o1 = x1;
}

// Sequential key chain: key(42)=(0,42); per step (partitionable fold-like split):
//   new_key = TF(key; 0,0), sub = TF(key; 0,1)
__global__ void keygen_kernel()
{
    if (threadIdx.x != 0) return;
    uint32_t k0 = 0u, k1 = 42u;
    for (int t = 0; t < N_STEPS; t++) {
        uint32_t ks2 = k0 ^ k1 ^ 0x1BD11BDAu;
        uint32_t n0, n1, s0, s1;
        threefry2x32(k0, k1, ks2, 0u, 0u, n0, n1);
        threefry2x32(k0, k1, ks2, 0u, 1u, s0, s1);
        g_subkeys[t] = make_uint2(s0, s1);
        k0 = n0; k1 = n1;
    }
}

// One warp per ant, persistent over all 511 steps. 16 nodes per lane.
__global__ void __launch_bounds__(256) ants_kernel(const float* __restrict__ pher,
                                                   const float* __restrict__ heur,
                                                   const int*   __restrict__ pos)
{
    const int warp = (blockIdx.x * blockDim.x + threadIdx.x) >> 5;
    const int lane = threadIdx.x & 31;
    if (warp >= N_ANTS) return;
    const int a = warp;
    const int nbase = lane * 16;

    const int p = pos[a];
    uint32_t vis = 0u;
    if ((p >> 4) == lane) vis |= 1u << (p & 15);
    int cur = p;
    float plen = 0.0f;
    if (lane == 0) g_paths[a * N_NODES] = p;

    const uint32_t idx0 = (uint32_t)a * N_NODES + (uint32_t)nbase;
    const float TINYF = 1.17549435e-38f;          // FLT_MIN (jax uniform minval)
    const float KTHR  = 1.0020020f;               // exp(0.002): 2x safety over max logit 0.001

    for (int step = 0; step < N_STEPS; step++) {
        const uint2 sk = g_subkeys[step];
        const uint32_t ks0 = sk.x, ks1 = sk.y;
        const uint32_t ks2 = ks0 ^ ks1 ^ 0x1BD11BDAu;

        uint32_t m[16];
        uint32_t m1, m2 = 0u; int i1 = nbase;
        {   // j = 0
            uint32_t o0, o1;
            threefry2x32(ks0, ks1, ks2, 0u, idx0, o0, o1);
            m[0] = (o0 ^ o1) >> 9;
            m1 = m[0];
        }
#pragma unroll
        for (int j = 1; j < 16; j++) {
            uint32_t o0, o1;
            threefry2x32(ks0, ks1, ks2, 0u, idx0 + (uint32_t)j, o0, o1);
            const uint32_t mm = (o0 ^ o1) >> 9;
            m[j] = mm;
            if (mm > m1)      { m2 = m1; m1 = mm; i1 = nbase + j; }
            else if (mm > m2) { m2 = mm; }
        }

        // Warp all-reduce of top-2 (ties collapse m2==m1 -> exact path below)
#pragma unroll
        for (int ofs = 16; ofs > 0; ofs >>= 1) {
            const uint32_t om1 = __shfl_xor_sync(0xFFFFFFFFu, m1, ofs);
            const uint32_t om2 = __shfl_xor_sync(0xFFFFFFFFu, m2, ofs);
            const int      oi1 = __shfl_xor_sync(0xFFFFFFFFu, i1, ofs);
            if (om1 > m1) { m2 = max(m1, om2); m1 = om1; i1 = oi1; }
            else          { m2 = max(m2, om1); }
        }

        int nxt;
        // Fast-path test: can second-best gumbel + max logit (0.001) possibly win?
        const float ftop = __uint_as_float(m1 | 0x3f800000u) - 1.0f;
        const float f2nd = __uint_as_float(m2 | 0x3f800000u) - 1.0f;
        const float la = -logf(fmaxf(ftop, TINYF));   // -log(u_top) > 0
        const float lb = -logf(fmaxf(f2nd, TINYF));   // -log(u_2nd) >= la
        if (lb >= la * KTHR) {
            nxt = i1;                                  // winner by >= 1e-3 real margin
        } else {
            // Exact reference computation for this (ant, step): full gumbel argmax.
            float best = -__int_as_float(0x7f800000);  // -inf
            int  besti = N_NODES;
#pragma unroll
            for (int j = 0; j < 16; j++) {
                const int n = nbase + j;
                const float f = __uint_as_float(m[j] | 0x3f800000u) - 1.0f;
                const float u = fmaxf(f, TINYF);
                const float g = -logf(-logf(u));
                const float h = __ldg(&heur[p * N_NODES + n]);
                const float b = __ldg(&pher[p * N_NODES + n]) * (h * h);
                const float l = ((vis >> j) & 1u) ? 0.0f : b;
                const float s = g + l;
                if (s > best) { best = s; besti = n; }  // first-index tie-break
            }
#pragma unroll
            for (int ofs = 16; ofs > 0; ofs >>= 1) {
                const float ob = __shfl_xor_sync(0xFFFFFFFFu, best, ofs);
                const int   oi = __shfl_xor_sync(0xFFFFFFFFu, besti, ofs);
                if (ob > best || (ob == best && oi < besti)) { best = ob; besti = oi; }
            }
            nxt = besti;
        }

        // plen accumulation in exact reference order (every lane, identical value)
        plen += __ldg(&heur[cur * N_NODES + nxt]);
        if ((nxt >> 4) == lane) vis |= 1u << (nxt & 15);
        if (lane == 0) g_paths[a * N_NODES + step + 1] = nxt;
        cur = nxt;
    }
    if (lane == 0) g_plen[a] = plen;
}

// First-index argmin over 16384 path lengths
__global__ void argmin_kernel()
{
    __shared__ float sv[1024];
    __shared__ int   si[1024];
    const int t = threadIdx.x;
    float bv = __int_as_float(0x7f800000);  // +inf
    int   bi = 0x7fffffff;
    for (int i = t; i < N_ANTS; i += 1024) {
        const float v = g_plen[i];
        if (v < bv || (v == bv && i < bi)) { bv = v; bi = i; }
    }
    sv[t] = bv; si[t] = bi;
    __syncthreads();
    for (int s = 512; s > 0; s >>= 1) {
        if (t < s) {
            const float ov = sv[t + s]; const int oi = si[t + s];
            if (ov < sv[t] || (ov == sv[t] && oi < si[t])) { sv[t] = ov; si[t] = oi; }
        }
        __syncthreads();
    }
    if (t == 0) g_best = si[0];
}

__global__ void bcast_kernel(float* __restrict__ out)
{
    const int i = blockIdx.x * blockDim.x + threadIdx.x;
    if (i < N_BATCH * N_NODES) {
        const int n = i & (N_NODES - 1);
        out[i] = (float)g_paths[g_best * N_NODES + n];
    }
}

extern "C" void kernel_launch(void* const* d_in, const int* in_sizes, int n_in,
                              void* d_out, int out_size)
{
    // metadata order: x, pheromone_trails, heuristic_info, ant_positions
    const float* pher = (const float*)d_in[1];
    const float* heur = (const float*)d_in[2];
    const int*   pos  = (const int*)d_in[3];
    float* out = (float*)d_out;

    keygen_kernel<<<1, 32>>>();
    ants_kernel<<<N_ANTS / 8, 256>>>(pher, heur, pos);
    argmin_kernel<<<1, 1024>>>();
    bcast_kernel<<<(N_BATCH * N_NODES + 255) / 256, 256>>>(out);
}

// round 3
// speedup vs baseline: 1.0759x; 1.0759x over previous
#include <cuda_runtime.h>
#include <stdint.h>

#define N_ANTS   16384
#define N_NODES  512
#define N_BATCH  4096
#define N_STEPS  511   // N_NODES - 1

// Scratch (no allocation allowed -> __device__ globals)
__device__ uint2  g_subkeys[N_STEPS];
__device__ int    g_paths[N_ANTS * N_NODES];
__device__ float  g_plen[N_ANTS];
__device__ int    g_best;

// Threefry round with the rotate expressed as a 64-bit multiply by 2^R:
//   lo = x1 << R, hi = x1 >> (32-R) come out of ONE IMAD.WIDE.U32 (fma pipe),
//   (lo | hi) ^ x0 is ONE LOP3 (alu pipe). Bit-identical to funnel-shift rotl.
__device__ __forceinline__ void tf_round(uint32_t& x0, uint32_t& x1, int R) {
    x0 += x1;
    unsigned long long w = (unsigned long long)x1 * (unsigned long long)(1u << R);
    x1 = ((uint32_t)w | (uint32_t)(w >> 32)) ^ x0;
}

// JAX threefry2x32: 20 rounds, 5 key injections.
__device__ __forceinline__ void threefry2x32(uint32_t ks0, uint32_t ks1, uint32_t ks2,
                                             uint32_t x0, uint32_t x1,
                                             uint32_t& o0, uint32_t& o1)
{
    x0 += ks0; x1 += ks1;
    tf_round(x0, x1, 13); tf_round(x0, x1, 15); tf_round(x0, x1, 26); tf_round(x0, x1, 6);
    x0 += ks1; x1 += ks2 + 1u;
    tf_round(x0, x1, 17); tf_round(x0, x1, 29); tf_round(x0, x1, 16); tf_round(x0, x1, 24);
    x0 += ks2; x1 += ks0 + 2u;
    tf_round(x0, x1, 13); tf_round(x0, x1, 15); tf_round(x0, x1, 26); tf_round(x0, x1, 6);
    x0 += ks0; x1 += ks1 + 3u;
    tf_round(x0, x1, 17); tf_round(x0, x1, 29); tf_round(x0, x1, 16); tf_round(x0, x1, 24);
    x0 += ks1; x1 += ks2 + 4u;
    tf_round(x0, x1, 13); tf_round(x0, x1, 15); tf_round(x0, x1, 26); tf_round(x0, x1, 6);
    x0 += ks2; x1 += ks0 + 5u;
    o0 = x0; o1 = x1;
}

// Sequential key chain: key(42)=(0,42); per step (partitionable fold-like split):
//   new_key = TF(key; 0,0), sub = TF(key; 0,1)
__global__ void keygen_kernel()
{
    if (threadIdx.x != 0) return;
    uint32_t k0 = 0u, k1 = 42u;
    for (int t = 0; t < N_STEPS; t++) {
        uint32_t ks2 = k0 ^ k1 ^ 0x1BD11BDAu;
        uint32_t n0, n1, s0, s1;
        threefry2x32(k0, k1, ks2, 0u, 0u, n0, n1);
        threefry2x32(k0, k1, ks2, 0u, 1u, s0, s1);
        g_subkeys[t] = make_uint2(s0, s1);
        k0 = n0; k1 = n1;
    }
}

// One warp per ant, persistent over all 511 steps. 16 nodes per lane.
__global__ void __launch_bounds__(256) ants_kernel(const float* __restrict__ pher,
                                                   const float* __restrict__ heur,
                                                   const int*   __restrict__ pos)
{
    __shared__ uint2 s_subkeys[N_STEPS];
    for (int i = threadIdx.x; i < N_STEPS; i += blockDim.x)
        s_subkeys[i] = g_subkeys[i];
    __syncthreads();

    const int warp = (blockIdx.x * blockDim.x + threadIdx.x) >> 5;
    const int lane = threadIdx.x & 31;
    if (warp >= N_ANTS) return;
    const int a = warp;
    const int nbase = lane * 16;

    const int p = pos[a];
    uint32_t vis = 0u;
    if ((p >> 4) == lane) vis |= 1u << (p & 15);
    int cur = p;
    float plen = 0.0f;
    if (lane == 0) g_paths[a * N_NODES] = p;

    const uint32_t idx0 = (uint32_t)a * N_NODES + (uint32_t)nbase;
    // Packed index complement: K = (31-lane)*16 + 15 ; K - j == K ^ j for j in [0,16)
    const uint32_t K = (uint32_t)((31 - lane) * 16 + 15);
    const float TINYF = 1.17549435e-38f;          // FLT_MIN (jax uniform minval)
    const float KTHR  = 1.0020020f;               // exp(0.002): 2x safety over max logit 0.001

    for (int step = 0; step < N_STEPS; step++) {
        const uint2 sk = s_subkeys[step];
        const uint32_t ks0 = sk.x, ks1 = sk.y;
        const uint32_t ks2 = ks0 ^ ks1 ^ 0x1BD11BDAu;

        // Top-2 of packed keys: high 23 bits = uniform mantissa, low 9 = 511-n
        uint32_t p1 = 0u, p2 = 0u;
#pragma unroll
        for (int j = 0; j < 16; j++) {
            uint32_t o0, o1;
            threefry2x32(ks0, ks1, ks2, 0u, idx0 + (uint32_t)j, o0, o1);
            const uint32_t pk = ((o0 ^ o1) & 0xFFFFFE00u) | (K ^ (uint32_t)j);
            const uint32_t t = min(p1, pk);
            p1 = max(p1, pk);
            p2 = max(p2, t);
        }

        // Warp all-reduce of top-2 packed values
#pragma unroll
        for (int ofs = 16; ofs > 0; ofs >>= 1) {
            const uint32_t q1 = __shfl_xor_sync(0xFFFFFFFFu, p1, ofs);
            const uint32_t q2 = __shfl_xor_sync(0xFFFFFFFFu, p2, ofs);
            const uint32_t t = min(p1, q1);
            p1 = max(p1, q1);
            p2 = max(p2, max(q2, t));
        }

        int nxt;
        // Fast-path test: can second-best gumbel + max logit (0.001) possibly win?
        const uint32_t m1 = p1 >> 9, m2 = p2 >> 9;
        const float ftop = __uint_as_float(m1 | 0x3f800000u) - 1.0f;
        const float f2nd = __uint_as_float(m2 | 0x3f800000u) - 1.0f;
        const float la = -logf(fmaxf(ftop, TINYF));   // -log(u_top) > 0
        const float lb = -logf(fmaxf(f2nd, TINYF));   // -log(u_2nd) >= la
        if (lb >= la * KTHR) {
            nxt = 511 - (int)(p1 & 0x1FFu);            // winner by >= 1e-3 real margin
        } else {
            // Exact reference computation for this (ant, step): full gumbel argmax.
            // Recompute the 16 threefry evals (rare: ~0.2% of ant-steps).
            float best = -__int_as_float(0x7f800000);  // -inf
            int  besti = N_NODES;
#pragma unroll
            for (int j = 0; j < 16; j++) {
                const int n = nbase + j;
                uint32_t o0, o1;
                threefry2x32(ks0, ks1, ks2, 0u, idx0 + (uint32_t)j, o0, o1);
                const uint32_t mm = (o0 ^ o1) >> 9;
                const float f = __uint_as_float(mm | 0x3f800000u) - 1.0f;
                const float u = fmaxf(f, TINYF);
                const float g = -logf(-logf(u));
                const float h = __ldg(&heur[p * N_NODES + n]);
                const float b = __ldg(&pher[p * N_NODES + n]) * (h * h);
                const float l = ((vis >> j) & 1u) ? 0.0f : b;
                const float s = g + l;
                if (s > best) { best = s; besti = n; }  // first-index tie-break
            }
#pragma unroll
            for (int ofs = 16; ofs > 0; ofs >>= 1) {
                const float ob = __shfl_xor_sync(0xFFFFFFFFu, best, ofs);
                const int   oi = __shfl_xor_sync(0xFFFFFFFFu, besti, ofs);
                if (ob > best || (ob == best && oi < besti)) { best = ob; besti = oi; }
            }
            nxt = besti;
        }

        // plen accumulation in exact reference order (every lane, identical value)
        plen += __ldg(&heur[cur * N_NODES + nxt]);
        if ((nxt >> 4) == lane) vis |= 1u << (nxt & 15);
        if (lane == 0) g_paths[a * N_NODES + step + 1] = nxt;
        cur = nxt;
    }
    if (lane == 0) g_plen[a] = plen;
}

// First-index argmin over 16384 path lengths
__global__ void argmin_kernel()
{
    __shared__ float sv[1024];
    __shared__ int   si[1024];
    const int t = threadIdx.x;
    float bv = __int_as_float(0x7f800000);  // +inf
    int   bi = 0x7fffffff;
    for (int i = t; i < N_ANTS; i += 1024) {
        const float v = g_plen[i];
        if (v < bv || (v == bv && i < bi)) { bv = v; bi = i; }
    }
    sv[t] = bv; si[t] = bi;
    __syncthreads();
    for (int s = 512; s > 0; s >>= 1) {
        if (t < s) {
            const float ov = sv[t + s]; const int oi = si[t + s];
            if (ov < sv[t] || (ov == sv[t] && oi < si[t])) { sv[t] = ov; si[t] = oi; }
        }
        __syncthreads();
    }
    if (t == 0) g_best = si[0];
}

__global__ void bcast_kernel(float* __restrict__ out)
{
    const int i = blockIdx.x * blockDim.x + threadIdx.x;
    if (i < N_BATCH * N_NODES) {
        const int n = i & (N_NODES - 1);
        out[i] = (float)g_paths[g_best * N_NODES + n];
    }
}

extern "C" void kernel_launch(void* const* d_in, const int* in_sizes, int n_in,
                              void* d_out, int out_size)
{
    // metadata order: x, pheromone_trails, heuristic_info, ant_positions
    const float* pher = (const float*)d_in[1];
    const float* heur = (const float*)d_in[2];
    const int*   pos  = (const int*)d_in[3];
    float* out = (float*)d_out;

    keygen_kernel<<<1, 32>>>();
    ants_kernel<<<N_ANTS / 8, 256>>>(pher, heur, pos);
    argmin_kernel<<<1, 1024>>>();
    bcast_kernel<<<(N_BATCH * N_NODES + 255) / 256, 256>>>(out);
}